// round 1
// baseline (speedup 1.0000x reference)
#include <cuda_runtime.h>
#include <math.h>

// ---------------- problem constants ----------------
#define TOT_N   128000      // B*N nodes
#define NEDGE   512000      // total edges
#define NB      128         // batch of graphs
#define HID     64          // H
#define NHEADS  4
#define DH      16
#define FIN     32
#define NLAYERS 4
#define AOUT    15
#define OBSD    1500
#define HSZ     512
#define VH      128
#define FEATD   (AOUT + OBSD)   // 1515

// ---------------- scratch (no allocs allowed) ----------------
__device__ float g_x  [TOT_N * HID];
__device__ float g_q  [TOT_N * HID];
__device__ float g_k  [TOT_N * HID];
__device__ float g_v  [TOT_N * HID];
__device__ float g_agg[TOT_N * HID];
__device__ float g_h  [TOT_N * 2 * HID];
__device__ int   g_cnt[TOT_N];
__device__ int   g_off[TOT_N + 1];
__device__ int   g_csr[NEDGE];
__device__ float g_feat[NB * FEATD];
__device__ float g_f1 [NB * HSZ];
__device__ float g_f2 [NB * HSZ];
__device__ float g_vh [NB * VH];
__device__ float g_vh2[NB * VH];

// ---------------- CSR build ----------------
__global__ void count_kernel(const int* __restrict__ dst) {
    int e = blockIdx.x * blockDim.x + threadIdx.x;
    if (e < NEDGE) atomicAdd(&g_cnt[dst[e]], 1);
}

__global__ void scan_kernel() {
    __shared__ int ssum[1024];
    int t = threadIdx.x;
    const int chunk = (TOT_N + 1023) / 1024;
    int start = t * chunk;
    int end = start + chunk; if (end > TOT_N) end = TOT_N;
    if (start > TOT_N) start = TOT_N;
    int s = 0;
    for (int i = start; i < end; i++) s += g_cnt[i];
    ssum[t] = s;
    __syncthreads();
    for (int d = 1; d < 1024; d <<= 1) {
        int v = 0;
        if (t >= d) v = ssum[t - d];
        __syncthreads();
        if (t >= d) ssum[t] += v;
        __syncthreads();
    }
    int run = (t > 0) ? ssum[t - 1] : 0;
    for (int i = start; i < end; i++) {
        int c = g_cnt[i];
        g_off[i] = run;
        run += c;
    }
    if (end == TOT_N) g_off[TOT_N] = run;  // last covering thread(s) write total
}

__global__ void scatter_kernel(const int* __restrict__ src, const int* __restrict__ dst) {
    int e = blockIdx.x * blockDim.x + threadIdx.x;
    if (e < NEDGE) {
        int d = dst[e];
        int pos = g_off[d] + atomicAdd(&g_cnt[d], 1);
        g_csr[pos] = src[e];
    }
}

// ---------------- per-(node,head) online-softmax attention ----------------
__global__ void attn_kernel(const float* __restrict__ q, const float* __restrict__ kk,
                            const float* __restrict__ vv, float* __restrict__ agg) {
    int idx = blockIdx.x * blockDim.x + threadIdx.x;
    if (idx >= TOT_N * NHEADS) return;
    int n = idx >> 2;
    int h = idx & 3;
    const float4* qp = (const float4*)(q + (size_t)n * HID + h * DH);
    float4 q0 = qp[0], q1 = qp[1], q2 = qp[2], q3 = qp[3];
    int e0 = g_off[n], e1 = g_off[n + 1];
    float M = -3.402823e38f, D = 0.f;
    float a[16];
#pragma unroll
    for (int i = 0; i < 16; i++) a[i] = 0.f;
    for (int e = e0; e < e1; e++) {
        int s = g_csr[e];
        const float4* kp = (const float4*)(kk + (size_t)s * HID + h * DH);
        float4 k0 = kp[0], k1 = kp[1], k2 = kp[2], k3 = kp[3];
        float dot = q0.x*k0.x + q0.y*k0.y + q0.z*k0.z + q0.w*k0.w
                  + q1.x*k1.x + q1.y*k1.y + q1.z*k1.z + q1.w*k1.w
                  + q2.x*k2.x + q2.y*k2.y + q2.z*k2.z + q2.w*k2.w
                  + q3.x*k3.x + q3.y*k3.y + q3.z*k3.z + q3.w*k3.w;
        dot *= 0.25f;  // 1/sqrt(DH)
        float Mn = fmaxf(M, dot);
        float sc = __expf(M - Mn);
        float w  = __expf(dot - Mn);
        D = D * sc + w;
        const float4* vp = (const float4*)(vv + (size_t)s * HID + h * DH);
        float4 v0 = vp[0], v1 = vp[1], v2 = vp[2], v3 = vp[3];
        a[0]  = a[0]*sc  + w*v0.x;  a[1]  = a[1]*sc  + w*v0.y;
        a[2]  = a[2]*sc  + w*v0.z;  a[3]  = a[3]*sc  + w*v0.w;
        a[4]  = a[4]*sc  + w*v1.x;  a[5]  = a[5]*sc  + w*v1.y;
        a[6]  = a[6]*sc  + w*v1.z;  a[7]  = a[7]*sc  + w*v1.w;
        a[8]  = a[8]*sc  + w*v2.x;  a[9]  = a[9]*sc  + w*v2.y;
        a[10] = a[10]*sc + w*v2.z;  a[11] = a[11]*sc + w*v2.w;
        a[12] = a[12]*sc + w*v3.x;  a[13] = a[13]*sc + w*v3.y;
        a[14] = a[14]*sc + w*v3.z;  a[15] = a[15]*sc + w*v3.w;
        M = Mn;
    }
    float inv = 1.f / (D + 1e-9f);
    float4* op = (float4*)(agg + (size_t)n * HID + h * DH);
    op[0] = make_float4(a[0]*inv,  a[1]*inv,  a[2]*inv,  a[3]*inv);
    op[1] = make_float4(a[4]*inv,  a[5]*inv,  a[6]*inv,  a[7]*inv);
    op[2] = make_float4(a[8]*inv,  a[9]*inv,  a[10]*inv, a[11]*inv);
    op[3] = make_float4(a[12]*inv, a[13]*inv, a[14]*inv, a[15]*inv);
}

// ---------------- per-thread-row GEMM (+ optional relu / bias / fused residual-LN) ------
// C[row, colOff..colOff+N) = A[row,:K] @ Bmat[:, colOff..colOff+N)  (+bias)(relu)(LN)
// colOff = blockIdx.y * N. LN requires N == full width, gridDim.y == 1.
template <int K, int N, bool RELU, bool HAS_BIAS, bool LN>
__global__ void __launch_bounds__(256)
gemm_rows(const float* __restrict__ A, const float* __restrict__ Bmat,
          const float* __restrict__ bias, const float* __restrict__ resid,
          const float* __restrict__ gamma, const float* __restrict__ beta,
          float* __restrict__ C, int M, int ldB, int ldC) {
    __shared__ float Bs[K * N];
    int colOff = blockIdx.y * N;
    for (int i = threadIdx.x; i < K * N; i += 256) {
        int kkk = i / N, nnn = i % N;
        Bs[i] = Bmat[(size_t)kkk * ldB + colOff + nnn];
    }
    __syncthreads();
    int row = blockIdx.x * 256 + threadIdx.x;
    if (row >= M) return;

    float acc[N];
#pragma unroll
    for (int n = 0; n < N; n++) acc[n] = 0.f;

    const float4* Arow = (const float4*)(A + (size_t)row * K);
#pragma unroll 4
    for (int k4 = 0; k4 < K / 4; k4++) {
        float4 av4 = Arow[k4];
        float av[4] = {av4.x, av4.y, av4.z, av4.w};
#pragma unroll
        for (int j = 0; j < 4; j++) {
            const float4* brow = (const float4*)(Bs + (k4 * 4 + j) * N);
            float a = av[j];
#pragma unroll
            for (int n4 = 0; n4 < N / 4; n4++) {
                float4 b = brow[n4];
                acc[n4 * 4 + 0] += a * b.x;
                acc[n4 * 4 + 1] += a * b.y;
                acc[n4 * 4 + 2] += a * b.z;
                acc[n4 * 4 + 3] += a * b.w;
            }
        }
    }
    if (HAS_BIAS) {
#pragma unroll
        for (int n = 0; n < N; n++) acc[n] += __ldg(&bias[colOff + n]);
    }
    if (RELU) {
#pragma unroll
        for (int n = 0; n < N; n++) acc[n] = fmaxf(acc[n], 0.f);
    }
    if (LN) {
        const float4* rr = (const float4*)(resid + (size_t)row * N);
#pragma unroll
        for (int n4 = 0; n4 < N / 4; n4++) {
            float4 r = rr[n4];
            acc[n4 * 4 + 0] += r.x;
            acc[n4 * 4 + 1] += r.y;
            acc[n4 * 4 + 2] += r.z;
            acc[n4 * 4 + 3] += r.w;
        }
        float mean = 0.f;
#pragma unroll
        for (int n = 0; n < N; n++) mean += acc[n];
        mean *= (1.f / N);
        float var = 0.f;
#pragma unroll
        for (int n = 0; n < N; n++) { float d = acc[n] - mean; var += d * d; }
        var *= (1.f / N);
        float rs = rsqrtf(var + 1e-5f);
#pragma unroll
        for (int n = 0; n < N; n++)
            acc[n] = (acc[n] - mean) * rs * __ldg(&gamma[n]) + __ldg(&beta[n]);
    }
    float4* co = (float4*)(C + (size_t)row * ldC + colOff);
#pragma unroll
    for (int n4 = 0; n4 < N / 4; n4++)
        co[n4] = make_float4(acc[n4*4+0], acc[n4*4+1], acc[n4*4+2], acc[n4*4+3]);
}

// ---------------- readout: gat_out into feat[:,0:15], copy obs into feat[:,15:1515] -----
__global__ void readout_kernel(const float* __restrict__ x, const int* __restrict__ agents,
                               const float* __restrict__ Wr, const float* __restrict__ br,
                               const float* __restrict__ obs, float* __restrict__ feat) {
    int row = blockIdx.x;  // 0..NB-1
    __shared__ float sx[HID];
    int node = agents[row];
    if (threadIdx.x < HID) sx[threadIdx.x] = x[(size_t)node * HID + threadIdx.x];
    __syncthreads();
    if (threadIdx.x < AOUT) {
        float acc = br[threadIdx.x];
        for (int k = 0; k < HID; k++) acc += sx[k] * Wr[k * AOUT + threadIdx.x];
        feat[(size_t)row * FEATD + threadIdx.x] = acc;
    }
    for (int i = threadIdx.x; i < OBSD; i += blockDim.x)
        feat[(size_t)row * FEATD + AOUT + i] = obs[(size_t)row * OBSD + i];
}

// ---------------- small FC: one block per row ----------------
__global__ void fc_kernel(const float* __restrict__ in, int ldIn,
                          const float* __restrict__ W, const float* __restrict__ bias,
                          float* __restrict__ out, int ldOut,
                          int K, int N, int act /*1=tanh*/) {
    extern __shared__ float s_in[];
    int row = blockIdx.x;
    for (int i = threadIdx.x; i < K; i += blockDim.x)
        s_in[i] = in[(size_t)row * ldIn + i];
    __syncthreads();
    int n = threadIdx.x;
    if (n >= N) return;
    float acc = bias ? __ldg(&bias[n]) : 0.f;
    int k = 0;
    for (; k + 4 <= K; k += 4) {
        acc += s_in[k]     * W[(size_t)k       * N + n];
        acc += s_in[k + 1] * W[(size_t)(k + 1) * N + n];
        acc += s_in[k + 2] * W[(size_t)(k + 2) * N + n];
        acc += s_in[k + 3] * W[(size_t)(k + 3) * N + n];
    }
    for (; k < K; k++) acc += s_in[k] * W[(size_t)k * N + n];
    if (act) acc = tanhf(acc);
    out[(size_t)row * ldOut + n] = acc;
}

// ---------------- launch ----------------
extern "C" void kernel_launch(void* const* d_in, const int* in_sizes, int n_in,
                              void* d_out, int out_size) {
    const float* node_feats = (const float*)d_in[0];
    const float* obs        = (const float*)d_in[1];
    const int*   edge_src   = (const int*)d_in[2];
    const int*   edge_dst   = (const int*)d_in[3];
    const int*   agents     = (const int*)d_in[4];
    const float* W_in = (const float*)d_in[5];
    const float* Wq   = (const float*)d_in[6];
    const float* Wk   = (const float*)d_in[7];
    const float* Wv   = (const float*)d_in[8];
    const float* Wo   = (const float*)d_in[9];
    const float* ln1g = (const float*)d_in[10];
    const float* ln1b = (const float*)d_in[11];
    const float* W1   = (const float*)d_in[12];
    const float* b1   = (const float*)d_in[13];
    const float* W2   = (const float*)d_in[14];
    const float* b2   = (const float*)d_in[15];
    const float* ln2g = (const float*)d_in[16];
    const float* ln2b = (const float*)d_in[17];
    const float* Wr   = (const float*)d_in[18];
    const float* br   = (const float*)d_in[19];
    const float* Wp1  = (const float*)d_in[20];
    const float* bp1  = (const float*)d_in[21];
    const float* Wp2  = (const float*)d_in[22];
    const float* bp2  = (const float*)d_in[23];
    const float* Wlog = (const float*)d_in[24];
    const float* blog = (const float*)d_in[25];
    const float* Wv1  = (const float*)d_in[26];
    const float* bv1  = (const float*)d_in[27];
    const float* Wv2  = (const float*)d_in[28];
    const float* bv2  = (const float*)d_in[29];
    const float* Wvo  = (const float*)d_in[30];
    const float* bvo  = (const float*)d_in[31];
    float* out = (float*)d_out;

    float *x_p, *q_p, *k_p, *v_p, *agg_p, *h_p, *feat_p, *f1_p, *f2_p, *vh_p, *vh2_p;
    int* cnt_p;
    cudaGetSymbolAddress((void**)&x_p,   g_x);
    cudaGetSymbolAddress((void**)&q_p,   g_q);
    cudaGetSymbolAddress((void**)&k_p,   g_k);
    cudaGetSymbolAddress((void**)&v_p,   g_v);
    cudaGetSymbolAddress((void**)&agg_p, g_agg);
    cudaGetSymbolAddress((void**)&h_p,   g_h);
    cudaGetSymbolAddress((void**)&feat_p, g_feat);
    cudaGetSymbolAddress((void**)&f1_p,  g_f1);
    cudaGetSymbolAddress((void**)&f2_p,  g_f2);
    cudaGetSymbolAddress((void**)&vh_p,  g_vh);
    cudaGetSymbolAddress((void**)&vh2_p, g_vh2);
    cudaGetSymbolAddress((void**)&cnt_p, g_cnt);

    const int GB = (TOT_N + 255) / 256;  // 500

    // CSR build (edges fixed per input, rebuilt every call for determinism rules)
    cudaMemsetAsync(cnt_p, 0, TOT_N * sizeof(int));
    count_kernel<<<(NEDGE + 255) / 256, 256>>>(edge_dst);
    scan_kernel<<<1, 1024>>>();
    cudaMemsetAsync(cnt_p, 0, TOT_N * sizeof(int));
    scatter_kernel<<<(NEDGE + 255) / 256, 256>>>(edge_src, edge_dst);

    // input projection: x = node_feats @ W_in
    gemm_rows<FIN, HID, false, false, false><<<GB, 256>>>(
        node_feats, W_in, nullptr, nullptr, nullptr, nullptr, x_p, TOT_N, HID, HID);

    for (int l = 0; l < NLAYERS; l++) {
        const float* wq = Wq + (size_t)l * HID * HID;
        const float* wk = Wk + (size_t)l * HID * HID;
        const float* wv = Wv + (size_t)l * HID * HID;
        const float* wo = Wo + (size_t)l * HID * HID;
        gemm_rows<HID, HID, false, false, false><<<GB, 256>>>(
            x_p, wq, nullptr, nullptr, nullptr, nullptr, q_p, TOT_N, HID, HID);
        gemm_rows<HID, HID, false, false, false><<<GB, 256>>>(
            x_p, wk, nullptr, nullptr, nullptr, nullptr, k_p, TOT_N, HID, HID);
        gemm_rows<HID, HID, false, false, false><<<GB, 256>>>(
            x_p, wv, nullptr, nullptr, nullptr, nullptr, v_p, TOT_N, HID, HID);

        attn_kernel<<<(TOT_N * NHEADS + 255) / 256, 256>>>(q_p, k_p, v_p, agg_p);

        // x = LN(x + agg @ Wo)
        gemm_rows<HID, HID, false, false, true><<<GB, 256>>>(
            agg_p, wo, nullptr, x_p, ln1g + l * HID, ln1b + l * HID, x_p, TOT_N, HID, HID);

        // h = relu(x @ W1 + b1)   [N = 128 -> 2 column tiles]
        gemm_rows<HID, HID, true, true, false><<<dim3(GB, 2), 256>>>(
            x_p, W1 + (size_t)l * HID * 2 * HID, b1 + (size_t)l * 2 * HID,
            nullptr, nullptr, nullptr, h_p, TOT_N, 2 * HID, 2 * HID);

        // x = LN(x + h @ W2 + b2)
        gemm_rows<2 * HID, HID, false, true, true><<<GB, 256>>>(
            h_p, W2 + (size_t)l * 2 * HID * HID, b2 + (size_t)l * HID,
            x_p, ln2g + l * HID, ln2b + l * HID, x_p, TOT_N, HID, HID);
    }

    // readout + concat with obs
    readout_kernel<<<NB, 256>>>(x_p, agents, Wr, br, obs, feat_p);

    // policy head
    fc_kernel<<<NB, HSZ, FEATD * sizeof(float)>>>(feat_p, FEATD, Wp1, bp1, f1_p, HSZ, FEATD, HSZ, 1);
    fc_kernel<<<NB, HSZ, HSZ * sizeof(float)>>>(f1_p, HSZ, Wp2, bp2, f2_p, HSZ, HSZ, HSZ, 1);
    fc_kernel<<<NB, HSZ, HSZ * sizeof(float)>>>(f2_p, HSZ, Wlog, blog, out, AOUT, HSZ, AOUT, 0);

    // value head
    fc_kernel<<<NB, 256, OBSD * sizeof(float)>>>(obs, OBSD, Wv1, bv1, vh_p, VH, OBSD, VH, 1);
    fc_kernel<<<NB, VH, VH * sizeof(float)>>>(vh_p, VH, Wv2, bv2, vh2_p, VH, VH, VH, 1);
    fc_kernel<<<NB, 32, VH * sizeof(float)>>>(vh2_p, VH, Wvo, bvo, out + NB * AOUT, 1, VH, 1, 0);
}